// round 2
// baseline (speedup 1.0000x reference)
#include <cuda_runtime.h>
#include <math.h>

// Encoder: B=2048, T=128, D=20, H=128
// softmax(hs[:,None] + xw) == softmax(xw)  (shift invariance over the D axis),
// so alpha is independent of the recurrent state: X_tilde and the input-side gate
// preactivations Gx are fully parallel. Only the per-batch h/c chain is sequential,
// and the 2048 chains are independent.

#define B_   2048
#define T_   128
#define D_   20
#define H_   128
#define G4   512          // 4*H
#define TS   127          // T-1
#define NB   16           // batches per block in recurrent kernel
#define NH   8            // batches per thread (two thread-halves of 128)

// Scratch (device-global: no allocations allowed anywhere)
__device__ float g_WT[H_ * G4];                  // W_hh transposed: [k][gate-unit]
__device__ float g_Gx[(size_t)B_ * TS * G4];     // x_tilde @ W_ih^T + b_ih + b_hh : [b][t][u]

typedef unsigned long long u64;

// ---- packed f32x2 helpers (Blackwell packed fp32 pipe; ptxas never emits these) ----
__device__ __forceinline__ u64 pk2(float lo, float hi) {
    u64 r; asm("mov.b64 %0, {%1,%2};" : "=l"(r) : "f"(lo), "f"(hi)); return r;
}
__device__ __forceinline__ void upk2(u64 v, float& lo, float& hi) {
    asm("mov.b64 {%0,%1}, %2;" : "=f"(lo), "=f"(hi) : "l"(v));
}
__device__ __forceinline__ u64 ffma2(u64 a, u64 b, u64 c) {
    u64 d; asm("fma.rn.f32x2 %0, %1, %2, %3;" : "=l"(d) : "l"(a), "l"(b), "l"(c)); return d;
}

// fast transcendentals: __expf rel err ~1e-6, compounds to <=1e-4 over 127 steps — safe vs 1e-3
__device__ __forceinline__ float sigf(float x) { return 1.0f / (1.0f + __expf(-x)); }
__device__ __forceinline__ float tanhf_fast(float x) {
    float ax = fabsf(x);
    float e  = __expf(-2.0f * ax);
    float r  = (1.0f - e) / (1.0f + e);
    return copysignf(r, x);
}

// ---------------------------------------------------------------------------
// Kernel 0: transpose W_hh (512,128) -> WT[k][u] so recurrent weight loads coalesce
// ---------------------------------------------------------------------------
__global__ void k0_transpose(const float* __restrict__ W_hh) {
    int idx = blockIdx.x * blockDim.x + threadIdx.x;
    if (idx < G4 * H_) {
        int u = idx >> 7;     // row of W_hh (gate-unit)
        int k = idx & 127;    // col (hidden index)
        g_WT[k * G4 + u] = W_hh[idx];
    }
}

// ---------------------------------------------------------------------------
// Kernel 1: per batch — xw, alpha=softmax(xw), X_tilde output, Gx precompute
// One block per batch element, 128 threads.
// ---------------------------------------------------------------------------
__global__ void __launch_bounds__(128) k1_attn_gx(
    const float* __restrict__ X, const float* __restrict__ W_attn,
    const float* __restrict__ W_ih, const float* __restrict__ b_ih,
    const float* __restrict__ b_hh, float* __restrict__ out_xt)
{
    __shared__ float Xs[T_ * D_];     // 2560 floats
    __shared__ float xw[D_];
    __shared__ float alpha[D_];

    const int tid = threadIdx.x;
    const int b   = blockIdx.x;
    const float* Xb = X + (size_t)b * T_ * D_;

    for (int i = tid; i < T_ * D_; i += 128) Xs[i] = Xb[i];
    __syncthreads();

    if (tid < D_) {
        const float* w_x = W_attn + 2 * H_;   // W_attn[0, 2H:2H+T]
        float s = 0.f;
        #pragma unroll 8
        for (int t = 0; t < T_; t++) s += Xs[t * D_ + tid] * w_x[t];
        xw[tid] = s;
    }
    __syncthreads();

    if (tid == 0) {
        float m = xw[0];
        #pragma unroll
        for (int d = 1; d < D_; d++) m = fmaxf(m, xw[d]);
        float e[D_]; float sum = 0.f;
        #pragma unroll
        for (int d = 0; d < D_; d++) { e[d] = expf(xw[d] - m); sum += e[d]; }
        float inv = 1.0f / sum;
        #pragma unroll
        for (int d = 0; d < D_; d++) alpha[d] = e[d] * inv;
    }
    __syncthreads();

    // X_tilde = alpha * X for t < T-1 ; keep scaled copy in smem for Gx
    float* xt_b = out_xt + (size_t)b * TS * D_;
    for (int i = tid; i < TS * D_; i += 128) {
        float v = alpha[i % D_] * Xs[i];
        Xs[i]   = v;
        xt_b[i] = v;
    }
    __syncthreads();

    // Cache this thread's 4 W_ih rows (units tid, tid+128, tid+256, tid+384) as f32x2 pairs
    u64 wih[4][10];
    float bias[4];
    #pragma unroll
    for (int g = 0; g < 4; g++) {
        int u = tid + g * H_;
        const float* wr = W_ih + u * D_;
        #pragma unroll
        for (int p = 0; p < 10; p++) wih[g][p] = pk2(wr[2 * p], wr[2 * p + 1]);
        bias[g] = b_ih[u] + b_hh[u];
    }

    float* gx_b = g_Gx + (size_t)b * TS * G4;
    for (int t = 0; t < TS; t++) {
        const float* xr = Xs + t * D_;   // 8B-aligned (80*t bytes)
        u64 acc[4];
        #pragma unroll
        for (int g = 0; g < 4; g++) acc[g] = pk2(bias[g], 0.f);
        #pragma unroll
        for (int p = 0; p < 10; p++) {
            u64 xv = *(const u64*)(xr + 2 * p);   // broadcast LDS.64
            #pragma unroll
            for (int g = 0; g < 4; g++) acc[g] = ffma2(wih[g][p], xv, acc[g]);
        }
        #pragma unroll
        for (int g = 0; g < 4; g++) {
            float lo, hi; upk2(acc[g], lo, hi);
            gx_b[t * G4 + tid + g * H_] = lo + hi;   // coalesced over tid
        }
    }
}

// ---------------------------------------------------------------------------
// Kernel 2: recurrent LSTM. 128 blocks (1/SM), NB=16 batches/block, 256 threads.
// Thread (j = tid&127, half = tid>>7) owns hidden unit j for 8 batches.
// W_hh streams from L1 (256KB working set, 1 block/SM -> mostly L1-resident);
// per-block L2 traffic amortized over 16 batches: total 4.2GB << fma time.
// h lives in smem as pre-packed f32 pairs. Inner product uses fma.rn.f32x2.
// Gx for timestep t is loaded at the top of t and folded in AFTER the k-loop,
// giving the DRAM loads the whole k-loop (~8K cyc) of latency hiding.
// ---------------------------------------------------------------------------
#define HP 18   // smem pitch (floats) for h rows: even (8B pair align), 2-way write conflicts

__global__ void __launch_bounds__(256) k2_lstm(float* __restrict__ out_xe)
{
    __shared__ float hs[H_ * HP];        // hs[k*HP + b] = h[k] for batch b0+b (b<16)

    const int tid  = threadIdx.x;
    const int j    = tid & 127;          // hidden unit
    const int half = tid >> 7;           // 0: batches 0-7, 1: batches 8-15
    const int b0   = blockIdx.x * NB;
    const int bo   = half * NH;          // batch offset within block

    float c[NH];
    #pragma unroll
    for (int b = 0; b < NH; b++) c[b] = 0.f;

    if (half == 0) {
        #pragma unroll
        for (int b = 0; b < 2 * NB; b += 2) {   // covers pitch incl. padding
            if (b < HP) hs[j * HP + b] = 0.f;
            if (b + 1 < HP) hs[j * HP + b + 1] = 0.f;
        }
    }
    __syncthreads();

    const float* gx_base = g_Gx + ((size_t)(b0 + bo)) * TS * G4 + j;
    const float* wt      = g_WT + j;
    float* xe0 = out_xe + ((size_t)(b0 + bo)) * TS * H_ + j;

    for (int t = 0; t < TS; t++) {
        // issue Gx loads early; consumed only after the k-loop
        float gxv[4][NH];
        #pragma unroll
        for (int g = 0; g < 4; g++)
            #pragma unroll
            for (int b = 0; b < NH; b++)
                gxv[g][b] = __ldg(gx_base + (size_t)b * TS * G4 + (size_t)t * G4 + g * H_);

        u64 acc[4][NH / 2];
        #pragma unroll
        for (int g = 0; g < 4; g++)
            #pragma unroll
            for (int q = 0; q < NH / 2; q++) acc[g][q] = 0ull;

        #pragma unroll 4
        for (int k = 0; k < H_; k++) {
            const float* hrow = hs + k * HP + bo;
            u64 h0 = *(const u64*)(hrow + 0);     // LDS.64 broadcast
            u64 h1 = *(const u64*)(hrow + 2);
            u64 h2 = *(const u64*)(hrow + 4);
            u64 h3 = *(const u64*)(hrow + 6);
            const float* wr = wt + k * G4;        // coalesced LDG, L1-resident
            float w0 = wr[0], w1 = wr[H_], w2 = wr[2 * H_], w3 = wr[3 * H_];
            u64 W0 = pk2(w0, w0), W1 = pk2(w1, w1), W2 = pk2(w2, w2), W3 = pk2(w3, w3);
            acc[0][0] = ffma2(W0, h0, acc[0][0]);  acc[0][1] = ffma2(W0, h1, acc[0][1]);
            acc[0][2] = ffma2(W0, h2, acc[0][2]);  acc[0][3] = ffma2(W0, h3, acc[0][3]);
            acc[1][0] = ffma2(W1, h0, acc[1][0]);  acc[1][1] = ffma2(W1, h1, acc[1][1]);
            acc[1][2] = ffma2(W1, h2, acc[1][2]);  acc[1][3] = ffma2(W1, h3, acc[1][3]);
            acc[2][0] = ffma2(W2, h0, acc[2][0]);  acc[2][1] = ffma2(W2, h1, acc[2][1]);
            acc[2][2] = ffma2(W2, h2, acc[2][2]);  acc[2][3] = ffma2(W2, h3, acc[2][3]);
            acc[3][0] = ffma2(W3, h0, acc[3][0]);  acc[3][1] = ffma2(W3, h1, acc[3][1]);
            acc[3][2] = ffma2(W3, h2, acc[3][2]);  acc[3][3] = ffma2(W3, h3, acc[3][3]);
        }

        // fold Gx in, unpack to per-batch gate preactivations
        float pre[4][NH];
        #pragma unroll
        for (int g = 0; g < 4; g++)
            #pragma unroll
            for (int q = 0; q < NH / 2; q++) {
                float lo, hi; upk2(acc[g][q], lo, hi);
                pre[g][2 * q]     = lo + gxv[g][2 * q];
                pre[g][2 * q + 1] = hi + gxv[g][2 * q + 1];
            }

        __syncthreads();                 // all reads of old h done
        float* hw = hs + j * HP + bo;
        #pragma unroll
        for (int b = 0; b < NH; b++) {
            float cn = sigf(pre[1][b]) * c[b] + sigf(pre[0][b]) * tanhf_fast(pre[2][b]);
            float hn = sigf(pre[3][b]) * tanhf_fast(cn);
            c[b]  = cn;
            hw[b] = hn;
            xe0[((size_t)b * TS + t) * H_] = hn;     // coalesced over j
        }
        __syncthreads();                 // new h visible before next k-loop
    }
}

// ---------------------------------------------------------------------------
// Launch
// ---------------------------------------------------------------------------
extern "C" void kernel_launch(void* const* d_in, const int* in_sizes, int n_in,
                              void* d_out, int out_size)
{
    const float* X      = (const float*)d_in[0];
    const float* W_attn = (const float*)d_in[1];
    // d_in[2] = b_attn: provably unused (softmax shift invariance)
    const float* W_ih   = (const float*)d_in[3];
    const float* W_hh   = (const float*)d_in[4];
    const float* b_ih   = (const float*)d_in[5];
    const float* b_hh   = (const float*)d_in[6];

    float* out    = (float*)d_out;
    float* out_xt = out;                               // X_tilde: (B, T-1, D)
    float* out_xe = out + (size_t)B_ * TS * D_;        // X_encoded: (B, T-1, H)

    k0_transpose<<<(G4 * H_ + 1023) / 1024, 1024>>>(W_hh);
    k1_attn_gx<<<B_, 128>>>(X, W_attn, W_ih, b_ih, b_hh, out_xt);
    k2_lstm<<<B_ / NB, 256>>>(out_xe);
}

// round 3
// speedup vs baseline: 1.4709x; 1.4709x over previous
#include <cuda_runtime.h>
#include <math.h>

// Encoder: B=2048, T=128, D=20, H=128
// softmax(hs[:,None] + xw) == softmax(xw)  (shift invariance over the D axis),
// so alpha is independent of the recurrent state: X_tilde and the input-side gate
// preactivations Gx are fully parallel. Only the per-batch h/c chain is sequential,
// and the 2048 chains are independent.

#define B_   2048
#define T_   128
#define D_   20
#define H_   128
#define G4   512          // 4*H
#define TS   127          // T-1
#define NB   16           // batches per block in recurrent kernel
#define NH   8            // batches per thread (two thread-halves of 128)

// Scratch (device-global: no allocations allowed anywhere)
// W_hh split by gate pair so the recurrent kernel's L1 working set fits:
//   g_Wif: gates i,f  -> loaded .ca (L1-resident, 128KB < ~218KB usable L1)
//   g_Wgo: gates g,o  -> loaded .cg (L2 only; never evicts the L1-resident half)
__device__ float g_Wif[H_ * 2 * H_];             // [k][{i,f}][j]
__device__ float g_Wgo[H_ * 2 * H_];             // [k][{g,o}][j]
__device__ float g_Gx[(size_t)B_ * TS * G4];     // x_tilde @ W_ih^T + b_ih + b_hh : [b][t][u]

typedef unsigned long long u64;

// ---- packed f32x2 helpers (Blackwell packed fp32 pipe; ptxas never emits these) ----
__device__ __forceinline__ u64 pk2(float lo, float hi) {
    u64 r; asm("mov.b64 %0, {%1,%2};" : "=l"(r) : "f"(lo), "f"(hi)); return r;
}
__device__ __forceinline__ void upk2(u64 v, float& lo, float& hi) {
    asm("mov.b64 {%0,%1}, %2;" : "=f"(lo), "=f"(hi) : "l"(v));
}
__device__ __forceinline__ u64 ffma2(u64 a, u64 b, u64 c) {
    u64 d; asm("fma.rn.f32x2 %0, %1, %2, %3;" : "=l"(d) : "l"(a), "l"(b), "l"(c)); return d;
}

// fast transcendentals: __expf rel err ~1e-6, compounds to <=1e-4 over 127 steps — safe vs 1e-3
__device__ __forceinline__ float sigf(float x) { return 1.0f / (1.0f + __expf(-x)); }
__device__ __forceinline__ float tanhf_fast(float x) {
    float ax = fabsf(x);
    float e  = __expf(-2.0f * ax);
    float r  = (1.0f - e) / (1.0f + e);
    return copysignf(r, x);
}

// ---------------------------------------------------------------------------
// Kernel 0: split + transpose W_hh (512,128) into [k][gatepair][j] layouts
// ---------------------------------------------------------------------------
__global__ void k0_transpose(const float* __restrict__ W_hh) {
    int idx = blockIdx.x * blockDim.x + threadIdx.x;
    if (idx < G4 * H_) {
        int u = idx >> 7;     // row of W_hh (gate-unit 0..511)
        int k = idx & 127;    // col (hidden index)
        int g = u >> 7;       // gate 0..3 (i,f,g,o)
        int j = u & 127;      // unit within gate
        float v = W_hh[idx];
        if (g < 2) g_Wif[k * 256 + g * 128 + j] = v;
        else       g_Wgo[k * 256 + (g - 2) * 128 + j] = v;
    }
}

// ---------------------------------------------------------------------------
// Kernel 1: per batch — xw, alpha=softmax(xw), X_tilde output, Gx precompute
// One block per batch element, 128 threads.
// ---------------------------------------------------------------------------
__global__ void __launch_bounds__(128) k1_attn_gx(
    const float* __restrict__ X, const float* __restrict__ W_attn,
    const float* __restrict__ W_ih, const float* __restrict__ b_ih,
    const float* __restrict__ b_hh, float* __restrict__ out_xt)
{
    __shared__ float Xs[T_ * D_];     // 2560 floats
    __shared__ float xw[D_];
    __shared__ float alpha[D_];

    const int tid = threadIdx.x;
    const int b   = blockIdx.x;
    const float* Xb = X + (size_t)b * T_ * D_;

    for (int i = tid; i < T_ * D_; i += 128) Xs[i] = Xb[i];
    __syncthreads();

    if (tid < D_) {
        const float* w_x = W_attn + 2 * H_;   // W_attn[0, 2H:2H+T]
        float s = 0.f;
        #pragma unroll 8
        for (int t = 0; t < T_; t++) s += Xs[t * D_ + tid] * w_x[t];
        xw[tid] = s;
    }
    __syncthreads();

    if (tid == 0) {
        float m = xw[0];
        #pragma unroll
        for (int d = 1; d < D_; d++) m = fmaxf(m, xw[d]);
        float e[D_]; float sum = 0.f;
        #pragma unroll
        for (int d = 0; d < D_; d++) { e[d] = expf(xw[d] - m); sum += e[d]; }
        float inv = 1.0f / sum;
        #pragma unroll
        for (int d = 0; d < D_; d++) alpha[d] = e[d] * inv;
    }
    __syncthreads();

    // X_tilde = alpha * X for t < T-1 ; keep scaled copy in smem for Gx
    float* xt_b = out_xt + (size_t)b * TS * D_;
    for (int i = tid; i < TS * D_; i += 128) {
        float v = alpha[i % D_] * Xs[i];
        Xs[i] = v;
        __stcs(xt_b + i, v);
    }
    __syncthreads();

    // Cache this thread's 4 W_ih rows (units tid, tid+128, tid+256, tid+384) as f32x2 pairs
    u64 wih[4][10];
    float bias[4];
    #pragma unroll
    for (int g = 0; g < 4; g++) {
        int u = tid + g * H_;
        const float* wr = W_ih + u * D_;
        #pragma unroll
        for (int p = 0; p < 10; p++) wih[g][p] = pk2(wr[2 * p], wr[2 * p + 1]);
        bias[g] = b_ih[u] + b_hh[u];
    }

    float* gx_b = g_Gx + (size_t)b * TS * G4;
    for (int t = 0; t < TS; t++) {
        const float* xr = Xs + t * D_;   // 8B-aligned (80*t bytes)
        u64 acc[4];
        #pragma unroll
        for (int g = 0; g < 4; g++) acc[g] = pk2(bias[g], 0.f);
        #pragma unroll
        for (int p = 0; p < 10; p++) {
            u64 xv = *(const u64*)(xr + 2 * p);   // broadcast LDS.64
            #pragma unroll
            for (int g = 0; g < 4; g++) acc[g] = ffma2(wih[g][p], xv, acc[g]);
        }
        #pragma unroll
        for (int g = 0; g < 4; g++) {
            float lo, hi; upk2(acc[g], lo, hi);
            __stcs(gx_b + t * G4 + tid + g * H_, lo + hi);   // coalesced, streaming
        }
    }
}

// ---------------------------------------------------------------------------
// Kernel 2: recurrent LSTM. 128 blocks (1/SM), NB=16 batches/block, 256 threads.
// Thread (j = tid&127, half = tid>>7) owns hidden unit j for 8 batches.
// Weight loads: i/f half .ca (L1-resident 128KB, no cyclic thrash);
//               g/o half .cg (L2-only, never evicts the L1 half; MLP hides lat).
// Gx loads .cs (streaming, no L1 pollution), folded into acc init.
// h lives in smem as f32 pairs. Inner product uses fma.rn.f32x2.
// ---------------------------------------------------------------------------
#define HP 18   // smem pitch (floats) for h rows: even (8B pair align)

__global__ void __launch_bounds__(256) k2_lstm(float* __restrict__ out_xe)
{
    __shared__ float hs[H_ * HP];        // hs[k*HP + b] = h[k] for batch b0+b (b<16)

    const int tid  = threadIdx.x;
    const int j    = tid & 127;          // hidden unit
    const int half = tid >> 7;           // 0: batches 0-7, 1: batches 8-15
    const int b0   = blockIdx.x * NB;
    const int bo   = half * NH;          // batch offset within block

    float c[NH];
    #pragma unroll
    for (int b = 0; b < NH; b++) c[b] = 0.f;

    if (half == 0) {
        #pragma unroll
        for (int b = 0; b < HP; b++) hs[j * HP + b] = 0.f;
    }
    __syncthreads();

    const float* gx_base = g_Gx + ((size_t)(b0 + bo)) * TS * G4 + j;
    const float* wif     = g_Wif + j;
    const float* wgo     = g_Wgo + j;
    float* xe0 = out_xe + ((size_t)(b0 + bo)) * TS * H_ + j;

    for (int t = 0; t < TS; t++) {
        // acc initialized directly from Gx (streaming loads; k-loop starts while in flight)
        u64 acc[4][NH / 2];
        {
            const float* gp = gx_base + (size_t)t * G4;
            #pragma unroll
            for (int g = 0; g < 4; g++)
                #pragma unroll
                for (int q = 0; q < NH / 2; q++) {
                    float lo = __ldcs(gp + (size_t)(2 * q)     * TS * G4 + g * H_);
                    float hi = __ldcs(gp + (size_t)(2 * q + 1) * TS * G4 + g * H_);
                    acc[g][q] = pk2(lo, hi);
                }
        }

        #pragma unroll 4
        for (int k = 0; k < H_; k++) {
            const float* hrow = hs + k * HP + bo;
            u64 h0 = *(const u64*)(hrow + 0);     // LDS.64 broadcast
            u64 h1 = *(const u64*)(hrow + 2);
            u64 h2 = *(const u64*)(hrow + 4);
            u64 h3 = *(const u64*)(hrow + 6);
            float w0 = wif[k * 256];              // .ca — L1-resident
            float w1 = wif[k * 256 + 128];
            float w2 = __ldcg(wgo + k * 256);     // .cg — L2 only
            float w3 = __ldcg(wgo + k * 256 + 128);
            u64 W0 = pk2(w0, w0), W1 = pk2(w1, w1), W2 = pk2(w2, w2), W3 = pk2(w3, w3);
            acc[0][0] = ffma2(W0, h0, acc[0][0]);  acc[0][1] = ffma2(W0, h1, acc[0][1]);
            acc[0][2] = ffma2(W0, h2, acc[0][2]);  acc[0][3] = ffma2(W0, h3, acc[0][3]);
            acc[1][0] = ffma2(W1, h0, acc[1][0]);  acc[1][1] = ffma2(W1, h1, acc[1][1]);
            acc[1][2] = ffma2(W1, h2, acc[1][2]);  acc[1][3] = ffma2(W1, h3, acc[1][3]);
            acc[2][0] = ffma2(W2, h0, acc[2][0]);  acc[2][1] = ffma2(W2, h1, acc[2][1]);
            acc[2][2] = ffma2(W2, h2, acc[2][2]);  acc[2][3] = ffma2(W2, h3, acc[2][3]);
            acc[3][0] = ffma2(W3, h0, acc[3][0]);  acc[3][1] = ffma2(W3, h1, acc[3][1]);
            acc[3][2] = ffma2(W3, h2, acc[3][2]);  acc[3][3] = ffma2(W3, h3, acc[3][3]);
        }

        // unpack to per-batch gate preactivations
        float pre[4][NH];
        #pragma unroll
        for (int g = 0; g < 4; g++)
            #pragma unroll
            for (int q = 0; q < NH / 2; q++) {
                float lo, hi; upk2(acc[g][q], lo, hi);
                pre[g][2 * q]     = lo;
                pre[g][2 * q + 1] = hi;
            }

        __syncthreads();                 // all reads of old h done
        float* hw = hs + j * HP + bo;
        #pragma unroll
        for (int b = 0; b < NH; b++) {
            float cn = sigf(pre[1][b]) * c[b] + sigf(pre[0][b]) * tanhf_fast(pre[2][b]);
            float hn = sigf(pre[3][b]) * tanhf_fast(cn);
            c[b]  = cn;
            hw[b] = hn;
            __stcs(xe0 + ((size_t)b * TS + t) * H_, hn);     // coalesced over j, streaming
        }
        __syncthreads();                 // new h visible before next k-loop
    }
}

// ---------------------------------------------------------------------------
// Launch
// ---------------------------------------------------------------------------
extern "C" void kernel_launch(void* const* d_in, const int* in_sizes, int n_in,
                              void* d_out, int out_size)
{
    const float* X      = (const float*)d_in[0];
    const float* W_attn = (const float*)d_in[1];
    // d_in[2] = b_attn: provably unused (softmax shift invariance)
    const float* W_ih   = (const float*)d_in[3];
    const float* W_hh   = (const float*)d_in[4];
    const float* b_ih   = (const float*)d_in[5];
    const float* b_hh   = (const float*)d_in[6];

    float* out    = (float*)d_out;
    float* out_xt = out;                               // X_tilde: (B, T-1, D)
    float* out_xe = out + (size_t)B_ * TS * D_;        // X_encoded: (B, T-1, H)

    k0_transpose<<<(G4 * H_ + 1023) / 1024, 1024>>>(W_hh);
    k1_attn_gx<<<B_, 128>>>(X, W_attn, W_ih, b_ih, b_hh, out_xt);
    k2_lstm<<<B_ / NB, 256>>>(out_xe);
}